// round 1
// baseline (speedup 1.0000x reference)
#include <cuda_runtime.h>
#include <cuda_bf16.h>
#include <math.h>

// Problem constants
#define BATCH 2
#define NPTS  4096
#define NG    (BATCH*NPTS)     // 8192 nodes total
#define DIM   128
#define MDIM  16
#define KNN_K 32
#define EH    530              // edge hidden dim (2*265)
#define NODE_IN 144            // DIM + MDIM
#define NODE_H  256

// -------------------- scratch (static device globals; no allocation) ----------
__device__ float d_A [NG * EH];       // feats @ We1[0:128]  + be1
__device__ float d_Bf[NG * EH];       // feats @ We1[128:256]
__device__ int   d_idx[NG * KNN_K];
__device__ float d_mi [NG * MDIM];
__device__ float d_nodein[NG * NODE_IN];
__device__ float d_h  [NG * NODE_H];

__device__ __forceinline__ float siluf(float x) {
    return x / (1.0f + __expf(-x));
}

// ------------------------------ KNN -------------------------------------------
// one block per query node; brute force distances + 32 argmin passes.
// key = (float_bits(dist) << 32) | j : ascending min == smallest dist, tie -> lowest j
__global__ __launch_bounds__(128) void knn_kernel(const float* __restrict__ coors)
{
    __shared__ float dist[NPTS];
    __shared__ unsigned long long keys[128];
    const int tid = threadIdx.x;
    const int g = blockIdx.x;
    const int boff = g & ~(NPTS - 1);

    const float cix = coors[g*3+0], ciy = coors[g*3+1], ciz = coors[g*3+2];
    for (int j = tid; j < NPTS; j += 128) {
        const int r = boff + j;
        float dx = cix - coors[r*3+0];
        float dy = ciy - coors[r*3+1];
        float dz = ciz - coors[r*3+2];
        dist[j] = dx*dx + dy*dy + dz*dz;
    }
    __syncthreads();

    for (int k = 0; k < KNN_K; k++) {
        unsigned long long best = 0xFFFFFFFFFFFFFFFFull;
        for (int j = tid; j < NPTS; j += 128) {
            unsigned long long key =
                ((unsigned long long)__float_as_uint(dist[j]) << 32) | (unsigned)j;
            if (key < best) best = key;
        }
        keys[tid] = best;
        __syncthreads();
        if (tid < 32) {
            unsigned long long v = keys[tid];
            unsigned long long t;
            t = keys[tid+32]; if (t < v) v = t;
            t = keys[tid+64]; if (t < v) v = t;
            t = keys[tid+96]; if (t < v) v = t;
            #pragma unroll
            for (int off = 16; off; off >>= 1) {
                unsigned long long o = __shfl_xor_sync(0xffffffffu, v, off);
                if (o < v) v = o;
            }
            if (tid == 0) {
                int sel = (int)(v & 0xFFFFFFFFull);
                d_idx[g*KNN_K + k] = sel;
                dist[sel] = __int_as_float(0x7F800000); // +inf
            }
        }
        __syncthreads();
    }
}

// ------------------------------ generic tiled GEMM ----------------------------
// Y[m][n] = act( sum_k X[m][k]*W[k][n] + bias[n] ) + resid[m][n]
// BM=BN=64, BK=16, 256 threads, 4x4 microtile. M must be a multiple of 64.
__global__ __launch_bounds__(256) void gemm_k(
    const float* __restrict__ X, int ldx,
    const float* __restrict__ W, int ldw,
    const float* __restrict__ bias,
    const float* __restrict__ resid, int ldr,
    float* __restrict__ Y, int ldy,
    int M, int N, int K, int act)
{
    __shared__ float Xs[16][64];
    __shared__ float Ws[16][64];
    const int tid = threadIdx.x;
    const int tm = tid >> 4, tn = tid & 15;
    const int m0 = blockIdx.y * 64, n0 = blockIdx.x * 64;

    float acc[4][4];
    #pragma unroll
    for (int i = 0; i < 4; i++)
        #pragma unroll
        for (int j = 0; j < 4; j++) acc[i][j] = 0.f;

    for (int k0 = 0; k0 < K; k0 += 16) {
        #pragma unroll
        for (int i = tid; i < 1024; i += 256) {
            int m = i >> 4, kk = i & 15;
            Xs[kk][m] = X[(size_t)(m0 + m) * ldx + k0 + kk];
        }
        #pragma unroll
        for (int i = tid; i < 1024; i += 256) {
            int kk = i >> 6, n = i & 63;
            int nn = n0 + n;
            Ws[kk][n] = (nn < N) ? W[(size_t)(k0 + kk) * ldw + nn] : 0.f;
        }
        __syncthreads();
        #pragma unroll
        for (int kk = 0; kk < 16; kk++) {
            float a[4], b[4];
            #pragma unroll
            for (int i = 0; i < 4; i++) a[i] = Xs[kk][tm*4 + i];
            #pragma unroll
            for (int j = 0; j < 4; j++) b[j] = Ws[kk][tn*4 + j];
            #pragma unroll
            for (int i = 0; i < 4; i++)
                #pragma unroll
                for (int j = 0; j < 4; j++) acc[i][j] += a[i] * b[j];
        }
        __syncthreads();
    }

    #pragma unroll
    for (int i = 0; i < 4; i++) {
        int r = m0 + tm*4 + i;
        #pragma unroll
        for (int j = 0; j < 4; j++) {
            int c = n0 + tn*4 + j;
            if (c < N) {
                float v = acc[i][j];
                if (bias)  v += bias[c];
                if (act)   v = siluf(v);
                if (resid) v += resid[(size_t)r * ldr + c];
                Y[(size_t)r * ldy + c] = v;
            }
        }
    }
}

// ------------------------------ fused edge kernel ------------------------------
// 128 threads = 4 warps; 4 nodes per block; warp owns a node (32 edges, groups of 4).
__global__ __launch_bounds__(128) void edge_kernel(
    const float* __restrict__ coors,
    const float* __restrict__ We1,   // 265 x 530 row-major (rows 256..264 = fourier)
    const float* __restrict__ We2,   // 530 x 16
    const float* __restrict__ be2,   // 16
    const float* __restrict__ Wc1,   // 16 x 64
    const float* __restrict__ bc1,   // 64
    const float* __restrict__ Wc2,   // 64
    const float* __restrict__ bc2,   // 1
    float* __restrict__ out_coors)   // NG x 3
{
    extern __shared__ float sm[];
    float* sWe2T = sm;                   // [16][530]  (col-major of We2)
    float* sW1f  = sWe2T + 16*EH;        // [9][530]
    float* sWc1  = sW1f  + 9*EH;         // [16][64]
    float* sWc2  = sWc1  + 1024;         // [64]
    float* sbe2  = sWc2  + 64;           // [16]
    float* sbc1  = sbe2  + 16;           // [64]
    float* sA    = sbc1  + 64;           // [4][530]
    float* sfe   = sA    + 4*EH;         // [4 warps][4 edges][9]
    float* srel  = sfe   + 144;          // [4][4][3]
    int*   sj    = (int*)(srel + 48);    // [4][4]

    const int tid  = threadIdx.x;
    const int w    = tid >> 5;
    const int lane = tid & 31;

    for (int i = tid; i < 16*EH; i += 128) { int t = i / EH, k = i - t*EH; sWe2T[i] = We2[k*16 + t]; }
    for (int i = tid; i < 9*EH;  i += 128) sW1f[i] = We1[256*EH + i];
    for (int i = tid; i < 1024;  i += 128) sWc1[i] = Wc1[i];
    if (tid < 64) sWc2[tid] = Wc2[tid];
    if (tid < 64) sbc1[tid] = bc1[tid];
    if (tid < 16) sbe2[tid] = be2[tid];

    const int g = blockIdx.x * 4 + w;
    for (int k = lane; k < EH; k += 32) sA[w*EH + k] = d_A[(size_t)g*EH + k];
    __syncthreads();

    const float bc2v = bc2[0];
    const int boff = g & ~(NPTS - 1);
    const float cix = coors[g*3+0], ciy = coors[g*3+1], ciz = coors[g*3+2];

    float misum[MDIM];
    #pragma unroll
    for (int t = 0; t < MDIM; t++) misum[t] = 0.f;
    float cax = 0.f, cay = 0.f, caz = 0.f;

    for (int grp = 0; grp < 8; grp++) {
        if (lane < 4) {
            const int e = lane;
            const int j = d_idx[g*KNN_K + grp*4 + e];
            sj[w*4 + e] = j;
            const int r = boff + j;
            float rx = cix - coors[r*3+0];
            float ry = ciy - coors[r*3+1];
            float rz = ciz - coors[r*3+2];
            float d  = rx*rx + ry*ry + rz*rz;
            float* fp = sfe + (w*4 + e)*9;
            float s, c;
            sincosf(d,          &s, &c); fp[0] = s; fp[4] = c;
            sincosf(d*0.5f,     &s, &c); fp[1] = s; fp[5] = c;
            sincosf(d*0.25f,    &s, &c); fp[2] = s; fp[6] = c;
            sincosf(d*0.125f,   &s, &c); fp[3] = s; fp[7] = c;
            fp[8] = d;
            float* rp = srel + (w*4 + e)*3;
            rp[0] = rx; rp[1] = ry; rp[2] = rz;
        }
        __syncwarp();

        float fearr[4][9];
        #pragma unroll
        for (int e = 0; e < 4; e++)
            #pragma unroll
            for (int t = 0; t < 9; t++) fearr[e][t] = sfe[(w*4 + e)*9 + t];

        const float* Bp0 = d_Bf + (size_t)(boff + sj[w*4+0]) * EH;
        const float* Bp1 = d_Bf + (size_t)(boff + sj[w*4+1]) * EH;
        const float* Bp2 = d_Bf + (size_t)(boff + sj[w*4+2]) * EH;
        const float* Bp3 = d_Bf + (size_t)(boff + sj[w*4+3]) * EH;

        float acc[4][MDIM];
        #pragma unroll
        for (int e = 0; e < 4; e++)
            #pragma unroll
            for (int t = 0; t < MDIM; t++) acc[e][t] = 0.f;

        #pragma unroll 1
        for (int it = 0; it < 17; it++) {
            const int k = it*32 + lane;
            if (k < EH) {
                const float a = sA[w*EH + k];
                float f0 = a, f1 = a, f2 = a, f3 = a;
                #pragma unroll
                for (int t = 0; t < 9; t++) {
                    const float wv = sW1f[t*EH + k];
                    f0 += fearr[0][t] * wv;
                    f1 += fearr[1][t] * wv;
                    f2 += fearr[2][t] * wv;
                    f3 += fearr[3][t] * wv;
                }
                const float h0 = siluf(f0 + Bp0[k]);
                const float h1 = siluf(f1 + Bp1[k]);
                const float h2 = siluf(f2 + Bp2[k]);
                const float h3 = siluf(f3 + Bp3[k]);
                #pragma unroll
                for (int t = 0; t < MDIM; t++) {
                    const float wv = sWe2T[t*EH + k];
                    acc[0][t] += h0 * wv;
                    acc[1][t] += h1 * wv;
                    acc[2][t] += h2 * wv;
                    acc[3][t] += h3 * wv;
                }
            }
        }

        // butterfly reduce across the warp (sum over k-partials)
        #pragma unroll
        for (int off = 16; off; off >>= 1)
            #pragma unroll
            for (int e = 0; e < 4; e++)
                #pragma unroll
                for (int t = 0; t < MDIM; t++)
                    acc[e][t] += __shfl_xor_sync(0xffffffffu, acc[e][t], off);

        #pragma unroll
        for (int e = 0; e < 4; e++) {
            float m[MDIM];
            #pragma unroll
            for (int t = 0; t < MDIM; t++) {
                m[t] = siluf(acc[e][t] + sbe2[t]);
                misum[t] += m[t];
            }
            // coors MLP: 16 -> 64 (silu) -> 1
            float h1 = sbc1[lane];
            float h2 = sbc1[lane + 32];
            #pragma unroll
            for (int t = 0; t < MDIM; t++) {
                h1 += m[t] * sWc1[t*64 + lane];
                h2 += m[t] * sWc1[t*64 + 32 + lane];
            }
            float wp = siluf(h1) * sWc2[lane] + siluf(h2) * sWc2[lane + 32];
            #pragma unroll
            for (int off = 16; off; off >>= 1)
                wp += __shfl_xor_sync(0xffffffffu, wp, off);
            const float we = wp + bc2v;
            const float* rp = srel + (w*4 + e)*3;
            cax += we * rp[0];
            cay += we * rp[1];
            caz += we * rp[2];
        }
        __syncwarp();
    }

    if (lane == 0) {
        #pragma unroll
        for (int t = 0; t < MDIM; t++) d_mi[(size_t)g*MDIM + t] = misum[t];
        out_coors[g*3+0] = cax + cix;
        out_coors[g*3+1] = cay + ciy;
        out_coors[g*3+2] = caz + ciz;
    }
}

// build concat(feats, m_i) -> d_nodein
__global__ void nodein_kernel(const float* __restrict__ feats)
{
    int i = blockIdx.x * blockDim.x + threadIdx.x;
    if (i < NG * NODE_IN) {
        int gg = i / NODE_IN, c = i - gg * NODE_IN;
        d_nodein[i] = (c < DIM) ? feats[(size_t)gg*DIM + c]
                                : d_mi[(size_t)gg*MDIM + (c - DIM)];
    }
}

// ------------------------------ launch ----------------------------------------
extern "C" void kernel_launch(void* const* d_in, const int* in_sizes, int n_in,
                              void* d_out, int out_size)
{
    const float* feats = (const float*)d_in[0];
    const float* coors = (const float*)d_in[1];
    const float* We1   = (const float*)d_in[2];
    const float* be1   = (const float*)d_in[3];
    const float* We2   = (const float*)d_in[4];
    const float* be2   = (const float*)d_in[5];
    const float* Wc1   = (const float*)d_in[6];
    const float* bc1   = (const float*)d_in[7];
    const float* Wc2   = (const float*)d_in[8];
    const float* bc2   = (const float*)d_in[9];
    const float* Wn1   = (const float*)d_in[10];
    const float* bn1   = (const float*)d_in[11];
    const float* Wn2   = (const float*)d_in[12];
    const float* bn2   = (const float*)d_in[13];

    float* out_nodes = (float*)d_out;
    float* out_coors = out_nodes + (size_t)NG * DIM;

    float *pA, *pB, *pNI, *pH;
    cudaGetSymbolAddress((void**)&pA,  d_A);
    cudaGetSymbolAddress((void**)&pB,  d_Bf);
    cudaGetSymbolAddress((void**)&pNI, d_nodein);
    cudaGetSymbolAddress((void**)&pH,  d_h);

    // edge kernel dynamic smem
    const int smem_floats = 16*EH + 9*EH + 1024 + 64 + 16 + 64 + 4*EH + 144 + 48 + 16;
    const int smem_bytes  = smem_floats * 4;
    cudaFuncSetAttribute(edge_kernel, cudaFuncAttributeMaxDynamicSharedMemorySize, smem_bytes);

    // 1. KNN
    knn_kernel<<<NG, 128>>>(coors);

    // 2. A = feats @ We1[0:128] + be1 ; B = feats @ We1[128:256]
    {
        dim3 grid((EH + 63) / 64, NG / 64);
        gemm_k<<<grid, 256>>>(feats, DIM, We1,            EH, be1,  nullptr, 0, pA, EH, NG, EH, DIM, 0);
        gemm_k<<<grid, 256>>>(feats, DIM, We1 + 128*EH,   EH, nullptr, nullptr, 0, pB, EH, NG, EH, DIM, 0);
    }

    // 3. fused edge kernel: m_i + coors_out
    edge_kernel<<<NG / 4, 128, smem_bytes>>>(coors, We1, We2, be2, Wc1, bc1, Wc2, bc2, out_coors);

    // 4. node MLP
    nodein_kernel<<<(NG*NODE_IN + 255)/256, 256>>>(feats);
    {
        dim3 g1(NODE_H / 64, NG / 64);
        gemm_k<<<g1, 256>>>(pNI, NODE_IN, Wn1, NODE_H, bn1, nullptr, 0, pH, NODE_H, NG, NODE_H, NODE_IN, 1);
        dim3 g2(DIM / 64, NG / 64);
        gemm_k<<<g2, 256>>>(pH, NODE_H, Wn2, DIM, bn2, feats, DIM, out_nodes, DIM, NG, DIM, NODE_H, 0);
    }
}

// round 2
// speedup vs baseline: 1.1490x; 1.1490x over previous
#include <cuda_runtime.h>
#include <cuda_bf16.h>
#include <math.h>

// Problem constants
#define BATCH 2
#define NPTS  4096
#define NG    (BATCH*NPTS)     // 8192 nodes total
#define DIM   128
#define MDIM  16
#define KNN_K 32
#define EH    530              // edge hidden dim (2*265)
#define EHP   544              // padded to 17*32
#define NODE_IN 144            // DIM + MDIM
#define NODE_H  256
#define NPB   8                // nodes per edge-kernel block

// -------------------- scratch (static device globals; no allocation) ----------
__device__ float d_A [NG * EHP];      // feats @ We1[0:128] + be1   (cols 530..543 stay 0)
__device__ float d_Bf[NG * EHP];      // feats @ We1[128:256]       (cols 530..543 stay 0)
__device__ int   d_idx[NG * KNN_K];
__device__ float d_mi [NG * MDIM];
__device__ float d_nodein[NG * NODE_IN];
__device__ float d_h  [NG * NODE_H];

__device__ __forceinline__ float siluf(float x) {
    return x / (1.0f + __expf(-x));
}

// ---------------- packed f32x2 helpers (Blackwell FFMA2 path) ------------------
__device__ __forceinline__ unsigned long long pk2(float lo, float hi) {
    unsigned long long r; asm("mov.b64 %0, {%1,%2};" : "=l"(r) : "f"(lo), "f"(hi)); return r;
}
__device__ __forceinline__ void upk2(unsigned long long v, float &lo, float &hi) {
    asm("mov.b64 {%0,%1}, %2;" : "=f"(lo), "=f"(hi) : "l"(v));
}
__device__ __forceinline__ unsigned long long fma2(unsigned long long a,
                                                   unsigned long long b,
                                                   unsigned long long c) {
    unsigned long long d;
    asm("fma.rn.f32x2 %0, %1, %2, %3;" : "=l"(d) : "l"(a), "l"(b), "l"(c));
    return d;
}
__device__ __forceinline__ unsigned long long add2(unsigned long long a,
                                                   unsigned long long b) {
    unsigned long long d;
    asm("add.rn.f32x2 %0, %1, %2;" : "=l"(d) : "l"(a), "l"(b));
    return d;
}

// ------------------------------ KNN -------------------------------------------
__global__ __launch_bounds__(128) void knn_kernel(const float* __restrict__ coors)
{
    __shared__ float dist[NPTS];
    __shared__ unsigned long long keys[128];
    const int tid = threadIdx.x;
    const int g = blockIdx.x;
    const int boff = g & ~(NPTS - 1);

    const float cix = coors[g*3+0], ciy = coors[g*3+1], ciz = coors[g*3+2];
    for (int j = tid; j < NPTS; j += 128) {
        const int r = boff + j;
        float dx = cix - coors[r*3+0];
        float dy = ciy - coors[r*3+1];
        float dz = ciz - coors[r*3+2];
        dist[j] = dx*dx + dy*dy + dz*dz;
    }
    __syncthreads();

    for (int k = 0; k < KNN_K; k++) {
        unsigned long long best = 0xFFFFFFFFFFFFFFFFull;
        for (int j = tid; j < NPTS; j += 128) {
            unsigned long long key =
                ((unsigned long long)__float_as_uint(dist[j]) << 32) | (unsigned)j;
            if (key < best) best = key;
        }
        keys[tid] = best;
        __syncthreads();
        if (tid < 32) {
            unsigned long long v = keys[tid];
            unsigned long long t;
            t = keys[tid+32]; if (t < v) v = t;
            t = keys[tid+64]; if (t < v) v = t;
            t = keys[tid+96]; if (t < v) v = t;
            #pragma unroll
            for (int off = 16; off; off >>= 1) {
                unsigned long long o = __shfl_xor_sync(0xffffffffu, v, off);
                if (o < v) v = o;
            }
            if (tid == 0) {
                int sel = (int)(v & 0xFFFFFFFFull);
                d_idx[g*KNN_K + k] = sel;
                dist[sel] = __int_as_float(0x7F800000);
            }
        }
        __syncthreads();
    }
}

// ------------------------------ tiled GEMM 128x64 ------------------------------
// Y[m][n] = act( sum_k X[m][k]*W[k][n] + bias[n] ) + resid[m][n]
// BM=128, BN=64, BK=16, 256 threads, 8x4 microtile. M % 128 == 0, K % 16 == 0.
__global__ __launch_bounds__(256) void gemm_k(
    const float* __restrict__ X, int ldx,
    const float* __restrict__ W, int ldw,
    const float* __restrict__ bias,
    const float* __restrict__ resid, int ldr,
    float* __restrict__ Y, int ldy,
    int M, int N, int K, int act)
{
    __shared__ float Xs[16*128];
    __shared__ float Ws[16*64];
    const int tid = threadIdx.x;
    const int tm = tid >> 4, tn = tid & 15;
    const int m0 = blockIdx.y * 128, n0 = blockIdx.x * 64;

    float acc[8][4];
    #pragma unroll
    for (int i = 0; i < 8; i++)
        #pragma unroll
        for (int j = 0; j < 4; j++) acc[i][j] = 0.f;

    for (int k0 = 0; k0 < K; k0 += 16) {
        #pragma unroll
        for (int i = 0; i < 8; i++) {
            int idx = tid + i*256;
            int m = idx >> 4, kk = idx & 15;
            Xs[kk*128 + (m ^ (kk*2))] = X[(size_t)(m0 + m) * ldx + k0 + kk];
        }
        #pragma unroll
        for (int i = 0; i < 4; i++) {
            int idx = tid + i*256;
            int kk = idx >> 6, n = idx & 63;
            int nn = n0 + n;
            Ws[kk*64 + n] = (nn < N) ? W[(size_t)(k0 + kk) * ldw + nn] : 0.f;
        }
        __syncthreads();
        #pragma unroll
        for (int kk = 0; kk < 16; kk++) {
            float a[8];
            #pragma unroll
            for (int i = 0; i < 8; i++) a[i] = Xs[kk*128 + ((tm*8 + i) ^ (kk*2))];
            float4 bv = *(const float4*)(Ws + kk*64 + tn*4);
            float b[4] = {bv.x, bv.y, bv.z, bv.w};
            #pragma unroll
            for (int i = 0; i < 8; i++)
                #pragma unroll
                for (int j = 0; j < 4; j++) acc[i][j] = fmaf(a[i], b[j], acc[i][j]);
        }
        __syncthreads();
    }

    #pragma unroll
    for (int i = 0; i < 8; i++) {
        int r = m0 + tm*8 + i;
        #pragma unroll
        for (int j = 0; j < 4; j++) {
            int c = n0 + tn*4 + j;
            if (c < N) {
                float v = acc[i][j];
                if (bias)  v += bias[c];
                if (act)   v = siluf(v);
                if (resid) v += resid[(size_t)r * ldr + c];
                Y[(size_t)r * ldy + c] = v;
            }
        }
    }
}

// ------------------------------ fused edge kernel ------------------------------
// 256 threads = 8 warps; 8 nodes/block; warp owns a node; 16 groups of 2 edges.
__global__ __launch_bounds__(256, 2) void edge_kernel(
    const float* __restrict__ coors,
    const float* __restrict__ We1,   // 265 x 530 row-major (rows 256..264 = fourier)
    const float* __restrict__ We2,   // 530 x 16
    const float* __restrict__ be2,   // 16
    const float* __restrict__ Wc1,   // 16 x 64
    const float* __restrict__ bc1,   // 64
    const float* __restrict__ Wc2,   // 64
    const float* __restrict__ bc2,   // 1
    float* __restrict__ out_coors)   // NG x 3
{
    extern __shared__ float sm[];
    float* sWe2T = sm;                     // [544][20] (k-major, stride 20 => conflict-free LDS.128)
    float* sW1f  = sWe2T + EHP*20;         // [9][544]
    float* sA    = sW1f  + 9*EHP;          // [8][544]
    float* sWc1  = sA    + NPB*EHP;        // [16][64]
    float* sWc2  = sWc1  + 1024;           // [64]
    float* sbc1  = sWc2  + 64;             // [64]
    float* sbe2  = sbc1  + 64;             // [16]
    float* sfe   = sbe2  + 16;             // [8][32][9]
    float* srel  = sfe   + NPB*32*9;       // [8][32][3]
    int*   sj    = (int*)(srel + NPB*32*3);// [8][32]

    const int tid  = threadIdx.x;
    const int w    = tid >> 5;
    const int lane = tid & 31;

    for (int i = tid; i < EHP*16; i += 256) {
        int k = i >> 4, t = i & 15;
        sWe2T[k*20 + t] = (k < EH) ? We2[k*16 + t] : 0.f;
    }
    for (int i = tid; i < 9*EHP; i += 256) {
        int t = i / EHP, k = i - t*EHP;
        sW1f[i] = (k < EH) ? We1[(256 + t)*EH + k] : 0.f;
    }
    {
        const int g0 = blockIdx.x * NPB;
        for (int i = tid; i < NPB*EHP; i += 256)
            sA[i] = d_A[(size_t)g0*EHP + i];
    }
    for (int i = tid; i < 1024; i += 256) sWc1[i] = Wc1[i];
    if (tid < 64) sWc2[tid] = Wc2[tid];
    if (tid < 64) sbc1[tid] = bc1[tid];
    if (tid < 16) sbe2[tid] = be2[tid];

    const int g = blockIdx.x * NPB + w;
    const int boff = g & ~(NPTS - 1);
    const float cix = coors[g*3+0], ciy = coors[g*3+1], ciz = coors[g*3+2];
    const float bc2v = bc2[0];

    // precompute all 32 edges' fourier features + rel coords (one lane each)
    {
        const int j = d_idx[g*KNN_K + lane];
        sj[w*32 + lane] = j;
        const int r = boff + j;
        float rx = cix - coors[r*3+0];
        float ry = ciy - coors[r*3+1];
        float rz = ciz - coors[r*3+2];
        float d  = rx*rx + ry*ry + rz*rz;
        float* fp = sfe + (w*32 + lane)*9;
        float s, c;
        sincosf(d,        &s, &c); fp[0] = s; fp[4] = c;
        sincosf(d*0.5f,   &s, &c); fp[1] = s; fp[5] = c;
        sincosf(d*0.25f,  &s, &c); fp[2] = s; fp[6] = c;
        sincosf(d*0.125f, &s, &c); fp[3] = s; fp[7] = c;
        fp[8] = d;
        float* rp = srel + (w*32 + lane)*3;
        rp[0] = rx; rp[1] = ry; rp[2] = rz;
    }
    __syncthreads();

    float misum[MDIM];
    #pragma unroll
    for (int t = 0; t < MDIM; t++) misum[t] = 0.f;
    float cax = 0.f, cay = 0.f, caz = 0.f;

    #pragma unroll 1
    for (int grp = 0; grp < 16; grp++) {
        const int e0 = grp*2;
        float fe0[9], fe1[9];
        #pragma unroll
        for (int t = 0; t < 9; t++) {
            fe0[t] = sfe[(w*32 + e0    )*9 + t];
            fe1[t] = sfe[(w*32 + e0 + 1)*9 + t];
        }
        const float* B0 = d_Bf + (size_t)(boff + sj[w*32 + e0    ]) * EHP;
        const float* B1 = d_Bf + (size_t)(boff + sj[w*32 + e0 + 1]) * EHP;

        unsigned long long acc0[8], acc1[8];
        #pragma unroll
        for (int p = 0; p < 8; p++) { acc0[p] = 0ull; acc1[p] = 0ull; }

        #pragma unroll 1
        for (int it = 0; it < 17; it++) {
            const int k = it*32 + lane;
            const float a = sA[w*EHP + k];
            float f0 = a, f1 = a;
            #pragma unroll
            for (int t = 0; t < 9; t++) {
                const float wv = sW1f[t*EHP + k];
                f0 = fmaf(fe0[t], wv, f0);
                f1 = fmaf(fe1[t], wv, f1);
            }
            const float h0 = siluf(f0 + B0[k]);
            const float h1 = siluf(f1 + B1[k]);
            const unsigned long long h0p = pk2(h0, h0);
            const unsigned long long h1p = pk2(h1, h1);
            const ulonglong2* wp = (const ulonglong2*)(sWe2T + k*20);
            #pragma unroll
            for (int c = 0; c < 4; c++) {
                ulonglong2 w2 = wp[c];
                acc0[c*2]   = fma2(h0p, w2.x, acc0[c*2]);
                acc0[c*2+1] = fma2(h0p, w2.y, acc0[c*2+1]);
                acc1[c*2]   = fma2(h1p, w2.x, acc1[c*2]);
                acc1[c*2+1] = fma2(h1p, w2.y, acc1[c*2+1]);
            }
        }

        #pragma unroll
        for (int off = 16; off; off >>= 1) {
            #pragma unroll
            for (int p = 0; p < 8; p++) {
                acc0[p] = add2(acc0[p], __shfl_xor_sync(0xffffffffu, acc0[p], off));
                acc1[p] = add2(acc1[p], __shfl_xor_sync(0xffffffffu, acc1[p], off));
            }
        }

        #pragma unroll
        for (int e = 0; e < 2; e++) {
            float m[MDIM];
            #pragma unroll
            for (int p = 0; p < 8; p++) {
                float lo, hi;
                upk2(e ? acc1[p] : acc0[p], lo, hi);
                m[2*p] = lo; m[2*p+1] = hi;
            }
            #pragma unroll
            for (int t = 0; t < MDIM; t++) {
                m[t] = siluf(m[t] + sbe2[t]);
                misum[t] += m[t];
            }
            float hA = sbc1[lane];
            float hB = sbc1[lane + 32];
            #pragma unroll
            for (int t = 0; t < MDIM; t++) {
                hA = fmaf(m[t], sWc1[t*64 + lane], hA);
                hB = fmaf(m[t], sWc1[t*64 + 32 + lane], hB);
            }
            float wv = siluf(hA)*sWc2[lane] + siluf(hB)*sWc2[lane + 32];
            #pragma unroll
            for (int off = 16; off; off >>= 1)
                wv += __shfl_xor_sync(0xffffffffu, wv, off);
            const float we = wv + bc2v;
            const float* rp = srel + (w*32 + e0 + e)*3;
            cax = fmaf(we, rp[0], cax);
            cay = fmaf(we, rp[1], cay);
            caz = fmaf(we, rp[2], caz);
        }
    }

    if (lane == 0) {
        #pragma unroll
        for (int t = 0; t < MDIM; t++) d_mi[(size_t)g*MDIM + t] = misum[t];
        out_coors[g*3+0] = cax + cix;
        out_coors[g*3+1] = cay + ciy;
        out_coors[g*3+2] = caz + ciz;
    }
}

// build concat(feats, m_i) -> d_nodein
__global__ void nodein_kernel(const float* __restrict__ feats)
{
    int i = blockIdx.x * blockDim.x + threadIdx.x;
    if (i < NG * NODE_IN) {
        int gg = i / NODE_IN, c = i - gg * NODE_IN;
        d_nodein[i] = (c < DIM) ? feats[(size_t)gg*DIM + c]
                                : d_mi[(size_t)gg*MDIM + (c - DIM)];
    }
}

// ------------------------------ launch ----------------------------------------
extern "C" void kernel_launch(void* const* d_in, const int* in_sizes, int n_in,
                              void* d_out, int out_size)
{
    const float* feats = (const float*)d_in[0];
    const float* coors = (const float*)d_in[1];
    const float* We1   = (const float*)d_in[2];
    const float* be1   = (const float*)d_in[3];
    const float* We2   = (const float*)d_in[4];
    const float* be2   = (const float*)d_in[5];
    const float* Wc1   = (const float*)d_in[6];
    const float* bc1   = (const float*)d_in[7];
    const float* Wc2   = (const float*)d_in[8];
    const float* bc2   = (const float*)d_in[9];
    const float* Wn1   = (const float*)d_in[10];
    const float* bn1   = (const float*)d_in[11];
    const float* Wn2   = (const float*)d_in[12];
    const float* bn2   = (const float*)d_in[13];

    float* out_nodes = (float*)d_out;
    float* out_coors = out_nodes + (size_t)NG * DIM;

    float *pA, *pB, *pNI, *pH;
    cudaGetSymbolAddress((void**)&pA,  d_A);
    cudaGetSymbolAddress((void**)&pB,  d_Bf);
    cudaGetSymbolAddress((void**)&pNI, d_nodein);
    cudaGetSymbolAddress((void**)&pH,  d_h);

    const int smem_floats = EHP*20 + 9*EHP + NPB*EHP + 1024 + 64 + 64 + 16
                          + NPB*32*9 + NPB*32*3 + NPB*32;
    const int smem_bytes  = smem_floats * 4;
    cudaFuncSetAttribute(edge_kernel, cudaFuncAttributeMaxDynamicSharedMemorySize, smem_bytes);

    // 1. KNN
    knn_kernel<<<NG, 128>>>(coors);

    // 2. A = feats @ We1[0:128] + be1 ; B = feats @ We1[128:256]   (ld-out = 544)
    {
        dim3 grid((EH + 63) / 64, NG / 128);
        gemm_k<<<grid, 256>>>(feats, DIM, We1,          EH, be1,     nullptr, 0, pA, EHP, NG, EH, DIM, 0);
        gemm_k<<<grid, 256>>>(feats, DIM, We1 + 128*EH, EH, nullptr, nullptr, 0, pB, EHP, NG, EH, DIM, 0);
    }

    // 3. fused edge kernel: m_i + coors_out
    edge_kernel<<<NG / NPB, 256, smem_bytes>>>(coors, We1, We2, be2, Wc1, bc1, Wc2, bc2, out_coors);

    // 4. node MLP
    nodein_kernel<<<(NG*NODE_IN + 255)/256, 256>>>(feats);
    {
        dim3 g1(NODE_H / 64, NG / 128);
        gemm_k<<<g1, 256>>>(pNI, NODE_IN, Wn1, NODE_H, bn1, nullptr, 0, pH, NODE_H, NG, NODE_H, NODE_IN, 1);
        dim3 g2(DIM / 64, NG / 128);
        gemm_k<<<g2, 256>>>(pH, NODE_H, Wn2, DIM, bn2, feats, DIM, out_nodes, DIM, NG, DIM, NODE_H, 0);
    }
}

// round 3
// speedup vs baseline: 1.2416x; 1.0806x over previous
#include <cuda_runtime.h>
#include <cuda_bf16.h>
#include <math.h>

// Problem constants
#define BATCH 2
#define NPTS  4096
#define NG    (BATCH*NPTS)     // 8192 nodes total
#define DIM   128
#define MDIM  16
#define KNN_K 32
#define EH    530              // edge hidden dim (2*265)
#define EHP   544              // padded to 17*32
#define NODE_IN 144            // DIM + MDIM
#define NODE_H  256
#define NPB   8                // nodes per edge-kernel block

// -------------------- scratch (static device globals; no allocation) ----------
__device__ float d_A [NG * EHP];      // feats @ We1[0:128] + be1   (cols 530..543 stay 0)
__device__ float d_Bf[NG * EHP];      // feats @ We1[128:256]       (cols 530..543 stay 0)
__device__ int   d_idx[NG * KNN_K];
__device__ float d_mi [NG * MDIM];
__device__ float d_nodein[NG * NODE_IN];
__device__ float d_h  [NG * NODE_H];
__device__ float d_We2p[EHP * 16];    // zero-padded We2 (row k -> 16 cols)
__device__ float d_W1fp[9 * EHP];     // zero-padded fourier rows of We1

__device__ __forceinline__ float siluf(float x) {
    return x / (1.0f + __expf(-x));
}

// ---------------- packed f32x2 helpers (Blackwell FFMA2 path) ------------------
__device__ __forceinline__ unsigned long long pk2(float lo, float hi) {
    unsigned long long r; asm("mov.b64 %0, {%1,%2};" : "=l"(r) : "f"(lo), "f"(hi)); return r;
}
__device__ __forceinline__ void upk2(unsigned long long v, float &lo, float &hi) {
    asm("mov.b64 {%0,%1}, %2;" : "=f"(lo), "=f"(hi) : "l"(v));
}
__device__ __forceinline__ unsigned long long fma2(unsigned long long a,
                                                   unsigned long long b,
                                                   unsigned long long c) {
    unsigned long long d;
    asm("fma.rn.f32x2 %0, %1, %2, %3;" : "=l"(d) : "l"(a), "l"(b), "l"(c));
    return d;
}
__device__ __forceinline__ unsigned long long add2(unsigned long long a,
                                                   unsigned long long b) {
    unsigned long long d;
    asm("add.rn.f32x2 %0, %1, %2;" : "=l"(d) : "l"(a), "l"(b));
    return d;
}

// ---------------------- pad / transpose small weights --------------------------
__global__ void pad_weights_kernel(const float* __restrict__ We1,
                                   const float* __restrict__ We2)
{
    int i = blockIdx.x * blockDim.x + threadIdx.x;
    if (i < EHP * 16) {
        int k = i >> 4, t = i & 15;
        d_We2p[i] = (k < EH) ? We2[k * 16 + t] : 0.f;
    }
    if (i < 9 * EHP) {
        int t = i / EHP, k = i - t * EHP;
        d_W1fp[i] = (k < EH) ? We1[(256 + t) * EH + k] : 0.f;
    }
}

// ------------------------------ KNN -------------------------------------------
__global__ __launch_bounds__(256) void knn_kernel(const float* __restrict__ coors)
{
    __shared__ float dist[NPTS];
    __shared__ unsigned long long keys[256];
    const int tid = threadIdx.x;
    const int g = blockIdx.x;
    const int boff = g & ~(NPTS - 1);

    const float cix = coors[g*3+0], ciy = coors[g*3+1], ciz = coors[g*3+2];
    for (int j = tid; j < NPTS; j += 256) {
        const int r = boff + j;
        float dx = cix - coors[r*3+0];
        float dy = ciy - coors[r*3+1];
        float dz = ciz - coors[r*3+2];
        dist[j] = dx*dx + dy*dy + dz*dz;
    }
    __syncthreads();

    for (int k = 0; k < KNN_K; k++) {
        unsigned long long best = 0xFFFFFFFFFFFFFFFFull;
        #pragma unroll
        for (int s = 0; s < NPTS/256; s++) {
            int j = tid + s*256;
            unsigned long long key =
                ((unsigned long long)__float_as_uint(dist[j]) << 32) | (unsigned)j;
            if (key < best) best = key;
        }
        keys[tid] = best;
        __syncthreads();
        if (tid < 32) {
            unsigned long long v = keys[tid];
            #pragma unroll
            for (int o = 1; o < 8; o++) {
                unsigned long long t = keys[tid + o*32];
                if (t < v) v = t;
            }
            #pragma unroll
            for (int off = 16; off; off >>= 1) {
                unsigned long long o = __shfl_xor_sync(0xffffffffu, v, off);
                if (o < v) v = o;
            }
            if (tid == 0) {
                int sel = (int)(v & 0xFFFFFFFFull);
                d_idx[g*KNN_K + k] = sel;
                dist[sel] = __int_as_float(0x7F800000);
            }
        }
        __syncthreads();
    }
}

// ------------------------------ tiled GEMM 128x64 ------------------------------
__global__ __launch_bounds__(256) void gemm_k(
    const float* __restrict__ X, int ldx,
    const float* __restrict__ W, int ldw,
    const float* __restrict__ bias,
    const float* __restrict__ resid, int ldr,
    float* __restrict__ Y, int ldy,
    int M, int N, int K, int act)
{
    __shared__ float Xs[16*128];
    __shared__ float Ws[16*64];
    const int tid = threadIdx.x;
    const int tm = tid >> 4, tn = tid & 15;
    const int m0 = blockIdx.y * 128, n0 = blockIdx.x * 64;

    float acc[8][4];
    #pragma unroll
    for (int i = 0; i < 8; i++)
        #pragma unroll
        for (int j = 0; j < 4; j++) acc[i][j] = 0.f;

    for (int k0 = 0; k0 < K; k0 += 16) {
        #pragma unroll
        for (int i = 0; i < 8; i++) {
            int idx = tid + i*256;
            int m = idx >> 4, kk = idx & 15;
            Xs[kk*128 + (m ^ (kk*2))] = X[(size_t)(m0 + m) * ldx + k0 + kk];
        }
        #pragma unroll
        for (int i = 0; i < 4; i++) {
            int idx = tid + i*256;
            int kk = idx >> 6, n = idx & 63;
            int nn = n0 + n;
            Ws[kk*64 + n] = (nn < N) ? W[(size_t)(k0 + kk) * ldw + nn] : 0.f;
        }
        __syncthreads();
        #pragma unroll
        for (int kk = 0; kk < 16; kk++) {
            float a[8];
            #pragma unroll
            for (int i = 0; i < 8; i++) a[i] = Xs[kk*128 + ((tm*8 + i) ^ (kk*2))];
            float4 bv = *(const float4*)(Ws + kk*64 + tn*4);
            float b[4] = {bv.x, bv.y, bv.z, bv.w};
            #pragma unroll
            for (int i = 0; i < 8; i++)
                #pragma unroll
                for (int j = 0; j < 4; j++) acc[i][j] = fmaf(a[i], b[j], acc[i][j]);
        }
        __syncthreads();
    }

    #pragma unroll
    for (int i = 0; i < 8; i++) {
        int r = m0 + tm*8 + i;
        #pragma unroll
        for (int j = 0; j < 4; j++) {
            int c = n0 + tn*4 + j;
            if (c < N) {
                float v = acc[i][j];
                if (bias)  v += bias[c];
                if (act)   v = siluf(v);
                if (resid) v += resid[(size_t)r * ldr + c];
                Y[(size_t)r * ldy + c] = v;
            }
        }
    }
}

// ------------------------------ fused edge kernel ------------------------------
// 256 threads = 8 warps; 8 nodes/block; warp owns a node; 16 groups of 2 edges.
// We2 / W1f weights are fetched from global (L1-resident, fully coalesced).
__global__ __launch_bounds__(256, 2) void edge_kernel(
    const float* __restrict__ coors,
    const float* __restrict__ be2,   // 16
    const float* __restrict__ Wc1,   // 16 x 64
    const float* __restrict__ bc1,   // 64
    const float* __restrict__ Wc2,   // 64
    const float* __restrict__ bc2,   // 1
    float* __restrict__ out_coors)   // NG x 3
{
    __shared__ float sA[NPB*EHP];
    __shared__ float sWc1[16*64];
    __shared__ float sWc2[64];
    __shared__ float sbc1[64];
    __shared__ float sbe2[16];
    __shared__ float sfe[NPB*32*9];
    __shared__ float srel[NPB*32*3];
    __shared__ int   sj[NPB*32];

    const int tid  = threadIdx.x;
    const int w    = tid >> 5;
    const int lane = tid & 31;

    {
        const int g0 = blockIdx.x * NPB;
        for (int i = tid; i < NPB*EHP; i += 256)
            sA[i] = d_A[(size_t)g0*EHP + i];
    }
    for (int i = tid; i < 1024; i += 256) sWc1[i] = Wc1[i];
    if (tid < 64) sWc2[tid] = Wc2[tid];
    if (tid < 64) sbc1[tid] = bc1[tid];
    if (tid < 16) sbe2[tid] = be2[tid];

    const int g = blockIdx.x * NPB + w;
    const int boff = g & ~(NPTS - 1);
    const float cix = coors[g*3+0], ciy = coors[g*3+1], ciz = coors[g*3+2];
    const float bc2v = bc2[0];

    // precompute all 32 edges' fourier features + rel coords (one lane each)
    {
        const int j = d_idx[g*KNN_K + lane];
        sj[w*32 + lane] = j;
        const int r = boff + j;
        float rx = cix - coors[r*3+0];
        float ry = ciy - coors[r*3+1];
        float rz = ciz - coors[r*3+2];
        float d  = rx*rx + ry*ry + rz*rz;
        float* fp = sfe + (w*32 + lane)*9;
        float s, c;
        sincosf(d,        &s, &c); fp[0] = s; fp[4] = c;
        sincosf(d*0.5f,   &s, &c); fp[1] = s; fp[5] = c;
        sincosf(d*0.25f,  &s, &c); fp[2] = s; fp[6] = c;
        sincosf(d*0.125f, &s, &c); fp[3] = s; fp[7] = c;
        fp[8] = d;
        float* rp = srel + (w*32 + lane)*3;
        rp[0] = rx; rp[1] = ry; rp[2] = rz;
    }
    __syncthreads();

    const int tcomp = lane & 15;      // output component this lane will own
    float misum_loc = 0.f;
    float cax = 0.f, cay = 0.f, caz = 0.f;

    #pragma unroll 1
    for (int grp = 0; grp < 16; grp++) {
        const int e0 = grp*2;
        float fe0[9], fe1[9];
        #pragma unroll
        for (int t = 0; t < 9; t++) {
            fe0[t] = sfe[(w*32 + e0    )*9 + t];
            fe1[t] = sfe[(w*32 + e0 + 1)*9 + t];
        }
        const float* B0 = d_Bf + (size_t)(boff + sj[w*32 + e0    ]) * EHP;
        const float* B1 = d_Bf + (size_t)(boff + sj[w*32 + e0 + 1]) * EHP;

        unsigned long long acc0[8], acc1[8];
        #pragma unroll
        for (int p = 0; p < 8; p++) { acc0[p] = 0ull; acc1[p] = 0ull; }

        #pragma unroll 1
        for (int it = 0; it < 17; it++) {
            const int k = it*32 + lane;
            const float a  = sA[w*EHP + k];
            const float b0 = B0[k];
            const float b1 = B1[k];
            float f0 = a + b0, f1 = a + b1;
            #pragma unroll
            for (int t = 0; t < 9; t++) {
                const float wv = d_W1fp[t*EHP + k];
                f0 = fmaf(fe0[t], wv, f0);
                f1 = fmaf(fe1[t], wv, f1);
            }
            const float h0 = siluf(f0);
            const float h1 = siluf(f1);
            const unsigned long long h0p = pk2(h0, h0);
            const unsigned long long h1p = pk2(h1, h1);
            const ulonglong2* wp = (const ulonglong2*)(d_We2p + (size_t)k*16);
            #pragma unroll
            for (int c = 0; c < 4; c++) {
                ulonglong2 w2 = wp[c];
                acc0[c*2]   = fma2(h0p, w2.x, acc0[c*2]);
                acc0[c*2+1] = fma2(h0p, w2.y, acc0[c*2+1]);
                acc1[c*2]   = fma2(h1p, w2.x, acc1[c*2]);
                acc1[c*2+1] = fma2(h1p, w2.y, acc1[c*2+1]);
            }
        }

        // reduce-scatter: final lane L holds m[L&15] of edge e0 + (L>>4)
        unsigned long long a8[8];
        #pragma unroll
        for (int p = 0; p < 8; p++) {
            unsigned long long s = (lane & 16) ? acc0[p] : acc1[p];
            unsigned long long r = __shfl_xor_sync(0xffffffffu, s, 16);
            a8[p] = add2((lane & 16) ? acc1[p] : acc0[p], r);
        }
        unsigned long long a4[4];
        #pragma unroll
        for (int q = 0; q < 4; q++) {
            unsigned long long s = (lane & 8) ? a8[q] : a8[q+4];
            unsigned long long r = __shfl_xor_sync(0xffffffffu, s, 8);
            a4[q] = add2((lane & 8) ? a8[q+4] : a8[q], r);
        }
        unsigned long long a2[2];
        #pragma unroll
        for (int q = 0; q < 2; q++) {
            unsigned long long s = (lane & 4) ? a4[q] : a4[q+2];
            unsigned long long r = __shfl_xor_sync(0xffffffffu, s, 4);
            a2[q] = add2((lane & 4) ? a4[q+2] : a4[q], r);
        }
        unsigned long long a1;
        {
            unsigned long long s = (lane & 2) ? a2[0] : a2[1];
            unsigned long long r = __shfl_xor_sync(0xffffffffu, s, 2);
            a1 = add2((lane & 2) ? a2[1] : a2[0], r);
        }
        float lo, hi; upk2(a1, lo, hi);
        {
            float s = (lane & 1) ? lo : hi;
            float r = __shfl_xor_sync(0xffffffffu, s, 1);
            lo = ((lane & 1) ? hi : lo) + r;
        }
        // lo = raw m component tcomp of this half's edge
        const float mv = siluf(lo + sbe2[tcomp]);
        misum_loc += mv;

        // rebuild full m[16] for own edge via idx-shuffle
        float mf[16];
        #pragma unroll
        for (int t = 0; t < MDIM; t++)
            mf[t] = __shfl_sync(0xffffffffu, mv, (lane & 16) | t);

        // coors MLP: each lane handles 4 hidden cols of its own edge
        float4 hb = *(const float4*)(sbc1 + tcomp*4);
        float h0 = hb.x, h1 = hb.y, h2 = hb.z, h3 = hb.w;
        #pragma unroll
        for (int t = 0; t < MDIM; t++) {
            float4 wv4 = *(const float4*)(sWc1 + t*64 + tcomp*4);
            h0 = fmaf(mf[t], wv4.x, h0);
            h1 = fmaf(mf[t], wv4.y, h1);
            h2 = fmaf(mf[t], wv4.z, h2);
            h3 = fmaf(mf[t], wv4.w, h3);
        }
        float4 c2 = *(const float4*)(sWc2 + tcomp*4);
        float wv = siluf(h0)*c2.x + siluf(h1)*c2.y + siluf(h2)*c2.z + siluf(h3)*c2.w;
        #pragma unroll
        for (int off = 8; off; off >>= 1)
            wv += __shfl_xor_sync(0xffffffffu, wv, off);
        const float we = wv + bc2v;
        const int eIdx = e0 + (lane >> 4);
        const float* rp = srel + (w*32 + eIdx)*3;
        cax = fmaf(we, rp[0], cax);
        cay = fmaf(we, rp[1], cay);
        caz = fmaf(we, rp[2], caz);
    }

    // combine halves
    cax += __shfl_xor_sync(0xffffffffu, cax, 16);
    cay += __shfl_xor_sync(0xffffffffu, cay, 16);
    caz += __shfl_xor_sync(0xffffffffu, caz, 16);
    float mtot = misum_loc + __shfl_xor_sync(0xffffffffu, misum_loc, 16);
    if (lane < 16) d_mi[(size_t)g*MDIM + lane] = mtot;
    if (lane == 0) {
        out_coors[g*3+0] = cax + cix;
        out_coors[g*3+1] = cay + ciy;
        out_coors[g*3+2] = caz + ciz;
    }
}

// build concat(feats, m_i) -> d_nodein
__global__ void nodein_kernel(const float* __restrict__ feats)
{
    int i = blockIdx.x * blockDim.x + threadIdx.x;
    if (i < NG * NODE_IN) {
        int gg = i / NODE_IN, c = i - gg * NODE_IN;
        d_nodein[i] = (c < DIM) ? feats[(size_t)gg*DIM + c]
                                : d_mi[(size_t)gg*MDIM + (c - DIM)];
    }
}

// ------------------------------ launch ----------------------------------------
extern "C" void kernel_launch(void* const* d_in, const int* in_sizes, int n_in,
                              void* d_out, int out_size)
{
    const float* feats = (const float*)d_in[0];
    const float* coors = (const float*)d_in[1];
    const float* We1   = (const float*)d_in[2];
    const float* be1   = (const float*)d_in[3];
    const float* We2   = (const float*)d_in[4];
    const float* be2   = (const float*)d_in[5];
    const float* Wc1   = (const float*)d_in[6];
    const float* bc1   = (const float*)d_in[7];
    const float* Wc2   = (const float*)d_in[8];
    const float* bc2   = (const float*)d_in[9];
    const float* Wn1   = (const float*)d_in[10];
    const float* bn1   = (const float*)d_in[11];
    const float* Wn2   = (const float*)d_in[12];
    const float* bn2   = (const float*)d_in[13];

    float* out_nodes = (float*)d_out;
    float* out_coors = out_nodes + (size_t)NG * DIM;

    float *pA, *pB, *pNI, *pH;
    cudaGetSymbolAddress((void**)&pA,  d_A);
    cudaGetSymbolAddress((void**)&pB,  d_Bf);
    cudaGetSymbolAddress((void**)&pNI, d_nodein);
    cudaGetSymbolAddress((void**)&pH,  d_h);

    // 0. padded weight copies
    pad_weights_kernel<<<(EHP*16 + 255)/256, 256>>>(We1, We2);

    // 1. KNN
    knn_kernel<<<NG, 256>>>(coors);

    // 2. A = feats @ We1[0:128] + be1 ; B = feats @ We1[128:256]   (ld-out = 544)
    {
        dim3 grid((EH + 63) / 64, NG / 128);
        gemm_k<<<grid, 256>>>(feats, DIM, We1,          EH, be1,     nullptr, 0, pA, EHP, NG, EH, DIM, 0);
        gemm_k<<<grid, 256>>>(feats, DIM, We1 + 128*EH, EH, nullptr, nullptr, 0, pB, EHP, NG, EH, DIM, 0);
    }

    // 3. fused edge kernel: m_i + coors_out
    edge_kernel<<<NG / NPB, 256>>>(coors, be2, Wc1, bc1, Wc2, bc2, out_coors);

    // 4. node MLP
    nodein_kernel<<<(NG*NODE_IN + 255)/256, 256>>>(feats);
    {
        dim3 g1(NODE_H / 64, NG / 128);
        gemm_k<<<g1, 256>>>(pNI, NODE_IN, Wn1, NODE_H, bn1, nullptr, 0, pH, NODE_H, NG, NODE_H, NODE_IN, 1);
        dim3 g2(DIM / 64, NG / 128);
        gemm_k<<<g2, 256>>>(pH, NODE_H, Wn2, DIM, bn2, feats, DIM, out_nodes, DIM, NG, DIM, NODE_H, 0);
    }
}